// round 17
// baseline (speedup 1.0000x reference)
#include <cuda_runtime.h>
#include <cstdint>
#include <math.h>

#define CH 512
#define NG 64
#define N_SAMP 16
#define H 64
#define W 64
#define HW 4096

#define TROWS 34                          // 32 rows + 2 halo
#define SCOLS 72                          // interior at col 4 -> 16B-aligned
#define CHT   (TROWS * SCOLS)             // 2448 floats
#define STILE (8 * CHT)                   // 19584 floats = 78336 B dynamic

// ===========================================================================
// Cluster(2) spatial halves per (group, sample). Grid (2,64,16) x 256 thr.
// 2 CTAs/SM -> independent CTAs overlap load/compute/store phases.
//  1. load own 32-row half (8 ch), partial stats -> part[16]
//  2. cluster.arrive; prep (d/bias/S from L2) hides cluster skew
//  3. cluster.wait; merge peer stat partials via DSMEM (16 floats)
//  4. conv + pointwise collapse + norm + multiply (R13 code)
// ===========================================================================
__global__ void __launch_bounds__(256, 2) __cluster_dims__(2, 1, 1)
fused_kernel(
    const float* __restrict__ content,
    const float* __restrict__ style,
    const float* __restrict__ dw_w,
    const float* __restrict__ dw_b,
    const float* __restrict__ pk_w,
    const float* __restrict__ pk_b,
    const float* __restrict__ pb_w,
    const float* __restrict__ pb_b,
    float* __restrict__ out)
{
    extern __shared__ float s[];          // [8][TROWS][SCOLS] content half-tile
    __shared__ float part[16];            // own stat partials [sum x8, sq x8]
    __shared__ float sd[512];             // style spatial mean
    __shared__ float dredW[72];           // d results per (j,pos)
    __shared__ float fd[72];
    __shared__ float fb[8], fm[8], fr[8];
    __shared__ float fS_sh;

    int hf = blockIdx.x;                  // 0 = top half, 1 = bottom
    int g  = blockIdx.y;
    int n  = blockIdx.z;
    int tid = threadIdx.x;
    int lane = tid & 31, warp = tid >> 5;
    int cbase = n * 512 + g * 8;
    int r0 = hf * 32;                     // first output row of this half

    // ============ 1. load own half (warp = channel), partial stats =========
    {
        int c = warp;
        const float* bc = content + (size_t)(cbase + c) * HW;
        float* sc = s + c * CHT;
        int sub = lane >> 4, q = lane & 15;
        float sum = 0.f, sq = 0.f;
        #pragma unroll
        for (int i = 0; i < 17; i++) {
            int lr = 2 * i + sub;                         // 0..33
            int gr = r0 - 1 + lr;
            gr = gr < 0 ? 1 : (gr > 63 ? 62 : gr);        // reflect
            float4 v = *(const float4*)(bc + gr * W + 4 * q);
            *(float4*)(sc + lr * SCOLS + 4 + 4 * q) = v;  // STS.128
            if (lr >= 1 && lr <= 32) {                    // interior rows
                sum += v.x + v.y + v.z + v.w;
                sq  += v.x * v.x + v.y * v.y + v.z * v.z + v.w * v.w;
            }
        }
        // halo columns: col 3 <- global col 1 ; col 68 <- global col 62
        for (int idx = tid; idx < 8 * TROWS; idx += 256) {
            int c2 = idx / TROWS, lr = idx % TROWS;
            int gr = r0 - 1 + lr;
            gr = gr < 0 ? 1 : (gr > 63 ? 62 : gr);
            const float* b2 = content + (size_t)(cbase + c2) * HW + gr * W;
            float* row = s + c2 * CHT + lr * SCOLS;
            row[3]  = b2[1];
            row[68] = b2[62];
        }
        #pragma unroll
        for (int off = 16; off; off >>= 1) {
            sum += __shfl_down_sync(0xffffffffu, sum, off);
            sq  += __shfl_down_sync(0xffffffffu, sq,  off);
        }
        if (lane == 0) { part[c] = sum; part[8 + c] = sq; }
    }
    __syncthreads();

    // ============ 2. cluster arrive; prep hides skew =======================
    asm volatile("barrier.cluster.arrive.aligned;" ::: "memory");

    // sd: thread handles channels tid and tid+256
    {
        #pragma unroll
        for (int t = 0; t < 2; t++) {
            int ch = tid + 256 * t;
            const float4* p = (const float4*)(style + (size_t)(n * 512 + ch) * 16);
            float4 b0 = p[0], b1 = p[1], b2 = p[2], b3 = p[3];
            float tot = b0.x + b0.y + b0.z + b0.w + b1.x + b1.y + b1.z + b1.w
                      + b2.x + b2.y + b2.z + b2.w + b3.x + b3.y + b3.z + b3.w;
            sd[ch] = tot * (1.f / 16.f);
        }
    }

    // d-dot: warp = j, lane covers 16 channels; style + weights from L2
    {
        int j = warp;
        const float4* w4base = (const float4*)dw_w;
        float acc[9];
        #pragma unroll
        for (int i = 0; i < 9; i++) acc[i] = 0.f;
        #pragma unroll
        for (int i = 0; i < 16; i++) {
            int ch = lane + 32 * i;
            float4 w = w4base[j * 512 + ch];
            const float4* stp = (const float4*)(style + (size_t)(n * 512 + ch) * 16);
            float4 s0 = stp[0], s1 = stp[1], s2 = stp[2], s3 = stp[3];
            float stv[16] = { s0.x, s0.y, s0.z, s0.w,  s1.x, s1.y, s1.z, s1.w,
                              s2.x, s2.y, s2.z, s2.w,  s3.x, s3.y, s3.z, s3.w };
            #pragma unroll
            for (int ky = 0; ky < 3; ky++)
                #pragma unroll
                for (int kx = 0; kx < 3; kx++)
                    acc[ky * 3 + kx] += w.x * stv[ky * 4 + kx]
                                      + w.y * stv[ky * 4 + kx + 1]
                                      + w.z * stv[ky * 4 + kx + 4]
                                      + w.w * stv[ky * 4 + kx + 5];
        }
        #pragma unroll
        for (int i = 0; i < 9; i++) {
            #pragma unroll
            for (int off = 16; off; off >>= 1)
                acc[i] += __shfl_xor_sync(0xffffffffu, acc[i], off);
        }
        if (lane == 0) {
            #pragma unroll
            for (int i = 0; i < 9; i++) dredW[j * 9 + i] = acc[i];
        }
    }
    __syncthreads();                      // sd + dredW ready

    // bias: warp = output channel
    {
        const float* row = pb_w + (size_t)(g * 8 + warp) * 512;
        float acc = 0.f;
        #pragma unroll
        for (int k = 0; k < 16; k++) {
            int c2 = lane + 32 * k;
            acc += row[c2] * sd[c2];
        }
        #pragma unroll
        for (int off = 16; off; off >>= 1)
            acc += __shfl_down_sync(0xffffffffu, acc, off);
        if (lane == 0) fb[warp] = acc + pb_b[g * 8 + warp];
    }
    // S: warp 0
    if (warp == 0) {
        const float4* pkw4 = (const float4*)pk_w;
        const float4* sd4  = (const float4*)sd;
        float4 sv0 = sd4[lane], sv1 = sd4[lane + 32];
        float4 sv2 = sd4[lane + 64], sv3 = sd4[lane + 96];
        float acc = 0.f;
        #pragma unroll
        for (int j = 0; j < 8; j++) {
            float4 w0 = pkw4[j * 128 + lane];
            float4 w1 = pkw4[j * 128 + lane + 32];
            float4 w2 = pkw4[j * 128 + lane + 64];
            float4 w3 = pkw4[j * 128 + lane + 96];
            acc += w0.x * sv0.x + w0.y * sv0.y + w0.z * sv0.z + w0.w * sv0.w
                 + w1.x * sv1.x + w1.y * sv1.y + w1.z * sv1.z + w1.w * sv1.w
                 + w2.x * sv2.x + w2.y * sv2.y + w2.z * sv2.z + w2.w * sv2.w
                 + w3.x * sv3.x + w3.y * sv3.y + w3.z * sv3.z + w3.w * sv3.w;
        }
        #pragma unroll
        for (int off = 16; off; off >>= 1)
            acc += __shfl_down_sync(0xffffffffu, acc, off);
        if (lane == 0) {
            float bsum = 0.f;
            #pragma unroll
            for (int j = 0; j < 8; j++) bsum += pk_b[j];
            fS_sh = acc + bsum;
        }
    }
    if (tid < 72) {
        float v = dredW[tid] + dw_b[tid / 9];
        fd[tid] = v >= 0.f ? v : 0.01f * v;           // leaky
    }

    // ============ 3. cluster wait; merge peer stat partials ================
    asm volatile("barrier.cluster.wait.aligned;" ::: "memory");
    if (tid < 8) {
        uint32_t my = (uint32_t)__cvta_generic_to_shared(part);
        uint32_t pa;
        uint32_t peer = hf ^ 1;
        asm("mapa.shared::cluster.u32 %0, %1, %2;" : "=r"(pa) : "r"(my), "r"(peer));
        float ps, pq;
        asm("ld.shared::cluster.f32 %0, [%1];" : "=f"(ps) : "r"(pa + 4u * tid));
        asm("ld.shared::cluster.f32 %0, [%1];" : "=f"(pq) : "r"(pa + 4u * (8 + tid)));
        float S = part[tid] + ps;
        float Q = part[8 + tid] + pq;
        float mean = S * (1.f / HW);
        float var  = (Q - S * S * (1.f / HW)) * (1.f / (HW - 1));   // ddof=1
        fm[tid] = mean;
        fr[tid] = rsqrtf(var + 1e-5f);
    }
    __syncthreads();

    // ============ 4. conv: 2 rows x 4 cols per thread ======================
    int r2 = tid >> 4;                    // 0..15
    int q4 = (tid & 15) * 4;              // output col base
    int h0 = 2 * r2;                      // local output rows h0, h0+1

    float D0[4] = {0.f, 0.f, 0.f, 0.f};
    float D1[4] = {0.f, 0.f, 0.f, 0.f};

    #pragma unroll
    for (int j = 0; j < 8; j++) {
        const float* sj = s + j * CHT;
        const float* fj = fd + j * 9;
        #pragma unroll
        for (int rr = 0; rr < 4; rr++) {
            const float* rp = sj + (h0 + rr) * SCOLS + q4;
            float vL = rp[3];
            float4 f4 = *(const float4*)(rp + 4);   // aligned LDS.128
            float vR = rp[8];
            if (rr < 3) {
                float a = fj[rr * 3], b2 = fj[rr * 3 + 1], cc2 = fj[rr * 3 + 2];
                D0[0] += a * vL   + b2 * f4.x + cc2 * f4.y;
                D0[1] += a * f4.x + b2 * f4.y + cc2 * f4.z;
                D0[2] += a * f4.y + b2 * f4.z + cc2 * f4.w;
                D0[3] += a * f4.z + b2 * f4.w + cc2 * vR;
            }
            if (rr >= 1) {
                int kr = rr - 1;
                float a = fj[kr * 3], b2 = fj[kr * 3 + 1], cc2 = fj[kr * 3 + 2];
                D1[0] += a * vL   + b2 * f4.x + cc2 * f4.y;
                D1[1] += a * f4.x + b2 * f4.y + cc2 * f4.z;
                D1[2] += a * f4.y + b2 * f4.z + cc2 * f4.w;
                D1[3] += a * f4.z + b2 * f4.w + cc2 * vR;
            }
        }
    }

    float S = fS_sh;
    float* obase = out + (size_t)cbase * HW + (r0 + h0) * W + q4;

    #pragma unroll
    for (int o = 0; o < 8; o++) {
        const float* so = s + o * CHT;
        float mo = fm[o], ro = fr[o], bo = fb[o];
        float4 r0v, r1v;
        {
            float4 cen = *(const float4*)(so + (h0 + 1) * SCOLS + 4 + q4);
            float p0 = D0[0] * S + bo, p1 = D0[1] * S + bo;
            float p2 = D0[2] * S + bo, p3 = D0[3] * S + bo;
            p0 = p0 >= 0.f ? p0 : 0.01f * p0;
            p1 = p1 >= 0.f ? p1 : 0.01f * p1;
            p2 = p2 >= 0.f ? p2 : 0.01f * p2;
            p3 = p3 >= 0.f ? p3 : 0.01f * p3;
            r0v.x = (cen.x - mo) * ro * p0;
            r0v.y = (cen.y - mo) * ro * p1;
            r0v.z = (cen.z - mo) * ro * p2;
            r0v.w = (cen.w - mo) * ro * p3;
        }
        {
            float4 cen = *(const float4*)(so + (h0 + 2) * SCOLS + 4 + q4);
            float p0 = D1[0] * S + bo, p1 = D1[1] * S + bo;
            float p2 = D1[2] * S + bo, p3 = D1[3] * S + bo;
            p0 = p0 >= 0.f ? p0 : 0.01f * p0;
            p1 = p1 >= 0.f ? p1 : 0.01f * p1;
            p2 = p2 >= 0.f ? p2 : 0.01f * p2;
            p3 = p3 >= 0.f ? p3 : 0.01f * p3;
            r1v.x = (cen.x - mo) * ro * p0;
            r1v.y = (cen.y - mo) * ro * p1;
            r1v.z = (cen.z - mo) * ro * p2;
            r1v.w = (cen.w - mo) * ro * p3;
        }
        __stcs((float4*)(obase + (size_t)o * HW),     r0v);
        __stcs((float4*)(obase + (size_t)o * HW + W), r1v);
    }

    // no CTA may exit while the peer can still read part[] via DSMEM
    asm volatile("barrier.cluster.arrive.aligned;" ::: "memory");
    asm volatile("barrier.cluster.wait.aligned;" ::: "memory");
}

// ===========================================================================
extern "C" void kernel_launch(void* const* d_in, const int* in_sizes, int n_in,
                              void* d_out, int out_size)
{
    const float* style   = (const float*)d_in[0];
    const float* content = (const float*)d_in[1];
    const float* dw_w    = (const float*)d_in[2];
    const float* dw_b    = (const float*)d_in[3];
    const float* pk_w    = (const float*)d_in[4];
    const float* pk_b    = (const float*)d_in[5];
    const float* pb_w    = (const float*)d_in[6];
    const float* pb_b    = (const float*)d_in[7];
    float* out = (float*)d_out;

    static bool attr_set = false;
    if (!attr_set) {
        cudaFuncSetAttribute(fused_kernel,
                             cudaFuncAttributeMaxDynamicSharedMemorySize,
                             STILE * sizeof(float));
        attr_set = true;
    }

    fused_kernel<<<dim3(2, NG, N_SAMP), 256, STILE * sizeof(float)>>>(
        content, style, dw_w, dw_b, pk_w, pk_b, pb_w, pb_b, out);
}